// round 15
// baseline (speedup 1.0000x reference)
#include <cuda_runtime.h>
#include <cuda_bf16.h>
#include <cstdint>

#define NN 50000
#define CC 128
#define EE 600000

// Scratch (device globals; no cudaMalloc allowed)
__device__ float g_x1[NN * CC];
__device__ float g_x2[NN * CC];
__device__ float g_yl[NN * CC];
__device__ float g_yr[NN * CC];
__device__ float g_yl2[NN * CC];   // layer-2 transform outputs (avoid WAR with combine1's gather)
__device__ float g_yr2[NN * CC];
__device__ int   g_cnt[NN];
__device__ int   g_rs[NN];
__device__ int   g_cur[NN];
__device__ int   g_csr[EE];
__device__ int   g_part[128];
// Pre-transposed bf16 hi/lo weights: [gemm(3)][n(128)][k(256)]
__device__ __nv_bfloat16 g_wbh[3 * 128 * 256];
__device__ __nv_bfloat16 g_wbl[3 * 128 * 256];

// ---------------------------------------------------------------------------
__device__ __forceinline__ uint32_t smem_u32(const void* p) {
    uint32_t a;
    asm("{ .reg .u64 t; cvta.to.shared.u64 t, %1; cvt.u32.u64 %0, t; }" : "=r"(a) : "l"(p));
    return a;
}
__device__ __forceinline__ void ldsm_x4(uint32_t& r0, uint32_t& r1, uint32_t& r2, uint32_t& r3,
                                        uint32_t addr) {
    asm volatile("ldmatrix.sync.aligned.m8n8.x4.shared.b16 {%0,%1,%2,%3}, [%4];"
                 : "=r"(r0), "=r"(r1), "=r"(r2), "=r"(r3) : "r"(addr));
}
__device__ __forceinline__ void mma_bf16(float* d, const uint32_t* a, uint32_t b0, uint32_t b1) {
    asm volatile(
        "mma.sync.aligned.m16n8k16.row.col.f32.bf16.bf16.f32 "
        "{%0,%1,%2,%3}, {%4,%5,%6,%7}, {%8,%9}, {%0,%1,%2,%3};"
        : "+f"(d[0]), "+f"(d[1]), "+f"(d[2]), "+f"(d[3])
        : "r"(a[0]), "r"(a[1]), "r"(a[2]), "r"(a[3]), "r"(b0), "r"(b1));
}
__device__ __forceinline__ void cp_async16(uint32_t dst, const void* src) {
    asm volatile("cp.async.cg.shared.global [%0], [%1], 16;" :: "r"(dst), "l"(src) : "memory");
}

// ---------------------------------------------------------------------------
// CSR build
__global__ void count_kernel(const int* __restrict__ ei, int* __restrict__ cnt, int E) {
    int i = blockIdx.x * blockDim.x + threadIdx.x;
    if (i < E) atomicAdd(&cnt[ei[E + i]], 1);
}

__global__ void scan_local_kernel(const int* __restrict__ cnt, int* __restrict__ rs,
                                  int* __restrict__ part, int n) {
    __shared__ int sh[512];
    int t = threadIdx.x;
    int i = blockIdx.x * 512 + t;
    int v = (i < n) ? cnt[i] : 0;
    sh[t] = v;
    __syncthreads();
#pragma unroll
    for (int off = 1; off < 512; off <<= 1) {
        int add = (t >= off) ? sh[t - off] : 0;
        __syncthreads();
        sh[t] += add;
        __syncthreads();
    }
    if (i < n) rs[i] = sh[t] - v;
    if (t == 511) part[blockIdx.x] = sh[511];
}

// every block re-scans the (<=128) partials in smem, then applies its offset
__global__ void scan_add_kernel(int* __restrict__ rs, const int* __restrict__ part,
                                int* __restrict__ cur, int n, int nb) {
    __shared__ int sh[128];
    int t = threadIdx.x;
    if (t < 128) sh[t] = (t < nb) ? part[t] : 0;
    __syncthreads();
#pragma unroll
    for (int off = 1; off < 128; off <<= 1) {
        int add = (t >= off && t < 128) ? sh[t - off] : 0;
        __syncthreads();
        if (t < 128) sh[t] += add;
        __syncthreads();
    }
    int boff = (blockIdx.x > 0) ? sh[blockIdx.x - 1] : 0;
    int i = blockIdx.x * 512 + t;
    if (i < n) {
        int v = rs[i] + boff;
        rs[i] = v;
        cur[i] = v;
    }
}

__global__ void fill_kernel(const int* __restrict__ ei, int* __restrict__ cur,
                            int* __restrict__ csr, int E) {
    int i = blockIdx.x * blockDim.x + threadIdx.x;
    if (i < E) {
        int slot = atomicAdd(&cur[ei[E + i]], 1);
        csr[slot] = ei[i];
    }
}

// ---------------------------------------------------------------------------
// combine: x_out[w] = relu(mean_agg(Y_l)[w] + bias + Y_r[w]) for w in [rowBase, rowBase+nRows)
__global__ __launch_bounds__(256) void combine_kernel(
    const float* __restrict__ yl, const float* __restrict__ yr,
    const int* __restrict__ csr, const int* __restrict__ rs,
    const int* __restrict__ cnt, const float* __restrict__ bias,
    float* __restrict__ out, int rowBase, int nRows) {
    int wi = (blockIdx.x * blockDim.x + threadIdx.x) >> 5;
    if (wi >= nRows) return;
    const int w = rowBase + wi;
    const int lane = threadIdx.x & 31;
    const int start = rs[w];
    const int deg = cnt[w];
    const int* nb = csr + start;

    float4 acc = make_float4(0.f, 0.f, 0.f, 0.f);
    int j = 0;
    for (; j + 4 <= deg; j += 4) {
        int s0 = __ldg(nb + j), s1 = __ldg(nb + j + 1);
        int s2 = __ldg(nb + j + 2), s3 = __ldg(nb + j + 3);
        float4 v0 = __ldg((const float4*)(yl + (size_t)s0 * CC) + lane);
        float4 v1 = __ldg((const float4*)(yl + (size_t)s1 * CC) + lane);
        float4 v2 = __ldg((const float4*)(yl + (size_t)s2 * CC) + lane);
        float4 v3 = __ldg((const float4*)(yl + (size_t)s3 * CC) + lane);
        acc.x += v0.x + v1.x + v2.x + v3.x;
        acc.y += v0.y + v1.y + v2.y + v3.y;
        acc.z += v0.z + v1.z + v2.z + v3.z;
        acc.w += v0.w + v1.w + v2.w + v3.w;
    }
    for (; j < deg; j++) {
        int s0 = __ldg(nb + j);
        float4 v0 = __ldg((const float4*)(yl + (size_t)s0 * CC) + lane);
        acc.x += v0.x; acc.y += v0.y; acc.z += v0.z; acc.w += v0.w;
    }
    float inv = 1.0f / (float)(deg > 0 ? deg : 1);
    float4 b = __ldg((const float4*)bias + lane);
    float4 r = __ldg((const float4*)(yr + (size_t)w * CC) + lane);
    float4 o;
    o.x = fmaxf(acc.x * inv + b.x + r.x, 0.f);
    o.y = fmaxf(acc.y * inv + b.y + r.y, 0.f);
    o.z = fmaxf(acc.z * inv + b.z + r.z, 0.f);
    o.w = fmaxf(acc.w * inv + b.w + r.w, 0.f);
    ((float4*)(out + (size_t)w * CC))[lane] = o;
}

// ---------------------------------------------------------------------------
// Weight prep: W[k][n] (row-major, 2x 128x128 stacked in k) -> Wt[n][k] bf16 hi/lo
__global__ void prep_w_kernel(const float* w0l, const float* w0r,
                              const float* w1l, const float* w1r,
                              const float* w2l, const float* w2r,
                              __nv_bfloat16* wh, __nv_bfloat16* wl) {
    int gid = blockIdx.x * blockDim.x + threadIdx.x;   // [g][n][k]
    if (gid >= 3 * 128 * 256) return;
    int g = gid >> 15;
    int rem = gid & 32767;
    int n = rem >> 8;
    int k = rem & 255;
    const float* W;
    if (g == 0)      W = (k < 128) ? w0l : w0r;
    else if (g == 1) W = (k < 128) ? w1l : w1r;
    else             W = (k < 128) ? w2l : w2r;
    float v = W[(size_t)(k & 127) * CC + n];
    __nv_bfloat16 h = __float2bfloat16(v);
    __nv_bfloat16 l = __float2bfloat16(v - __bfloat162float(h));
    wh[gid] = h;
    wl[gid] = l;
}

// ---------------------------------------------------------------------------
#define ROW_B 80

// Transform GEMM: Y_half = X (rows [rowBase, ...)) @ Wt[half]^T, half = blockIdx.y.
__global__ __launch_bounds__(256, 2) void gemm_t_kernel(
    const float* __restrict__ X,
    const __nv_bfloat16* __restrict__ wh, const __nv_bfloat16* __restrict__ wl,
    float* __restrict__ yl, float* __restrict__ yr, int rowBase, int M) {

    __shared__ __align__(16) char sA_hi[128 * ROW_B];
    __shared__ __align__(16) char sA_lo[128 * ROW_B];
    __shared__ __align__(16) char sB_hi[128 * ROW_B];
    __shared__ __align__(16) char sB_lo[128 * ROW_B];

    const int tid = threadIdx.x;
    const int lane = tid & 31;
    const int wid = tid >> 5;
    const int wm = (wid & 3) * 32;
    const int wn = (wid >> 2) * 64;
    const int row0 = rowBase + blockIdx.x * 128;
    const int half = blockIdx.y;
    float* out = half ? yr : yl;

    float acc[2][8][4] = {};

    const uint32_t aHi = smem_u32(sA_hi), aLo = smem_u32(sA_lo);
    const uint32_t bHi = smem_u32(sB_hi), bLo = smem_u32(sB_lo);

    const int a_mrow = ((lane >> 3) & 1) * 8 + (lane & 7);
    const int a_j = lane >> 4;
    const int b_nrow = (lane >> 4) * 8 + (lane & 7);
    const int b_j = (lane >> 3) & 1;

    float4 vA[4];

    auto loadA = [&](int c) {
        const int koff = c * 32;
#pragma unroll
        for (int i = 0; i < 4; i++) {
            int idx = tid + (i << 8);
            int m = idx >> 3, k4 = idx & 7;
            int row = row0 + m;
            vA[i] = (row < M) ? *(const float4*)(X + (size_t)row * CC + koff + (k4 << 2))
                              : make_float4(0.f, 0.f, 0.f, 0.f);
        }
    };

    loadA(0);

    for (int c = 0; c < 4; c++) {
        const int cb = half * 4 + c;
#pragma unroll
        for (int i = 0; i < 2; i++) {
            int idx = tid + (i << 8);
            int n = idx >> 2, j = idx & 3;
            size_t srcOff = (size_t)n * 512 + (size_t)cb * 64 + (size_t)j * 16;
            cp_async16(bHi + n * ROW_B + (j << 4), (const char*)wh + srcOff);
            cp_async16(bLo + n * ROW_B + (j << 4), (const char*)wl + srcOff);
        }
        asm volatile("cp.async.commit_group;" ::: "memory");

#pragma unroll
        for (int i = 0; i < 4; i++) {
            int idx = tid + (i << 8);
            int m = idx >> 3, k4 = idx & 7;
            float x0 = vA[i].x, x1 = vA[i].y, x2 = vA[i].z, x3 = vA[i].w;
            __nv_bfloat162 h01 = make_bfloat162(__float2bfloat16(x0), __float2bfloat16(x1));
            __nv_bfloat162 h23 = make_bfloat162(__float2bfloat16(x2), __float2bfloat16(x3));
            __nv_bfloat162 l01 = make_bfloat162(
                __float2bfloat16(x0 - __bfloat162float(h01.x)),
                __float2bfloat16(x1 - __bfloat162float(h01.y)));
            __nv_bfloat162 l23 = make_bfloat162(
                __float2bfloat16(x2 - __bfloat162float(h23.x)),
                __float2bfloat16(x3 - __bfloat162float(h23.y)));
            char* pd = sA_hi + m * ROW_B + (k4 << 3);
            *(__nv_bfloat162*)(pd + 0) = h01;
            *(__nv_bfloat162*)(pd + 4) = h23;
            char* pl = sA_lo + m * ROW_B + (k4 << 3);
            *(__nv_bfloat162*)(pl + 0) = l01;
            *(__nv_bfloat162*)(pl + 4) = l23;
        }

        if (c < 3) loadA(c + 1);

        asm volatile("cp.async.wait_group 0;" ::: "memory");
        __syncthreads();

#pragma unroll
        for (int ks = 0; ks < 2; ks++) {
            uint32_t ah[8], al[8];
#pragma unroll
            for (int mi = 0; mi < 2; mi++) {
                uint32_t off = (uint32_t)((wm + mi * 16 + a_mrow) * ROW_B + ks * 32 + a_j * 16);
                ldsm_x4(ah[mi * 4 + 0], ah[mi * 4 + 1], ah[mi * 4 + 2], ah[mi * 4 + 3], aHi + off);
                ldsm_x4(al[mi * 4 + 0], al[mi * 4 + 1], al[mi * 4 + 2], al[mi * 4 + 3], aLo + off);
            }
#pragma unroll
            for (int bg = 0; bg < 4; bg++) {
                uint32_t off = (uint32_t)((wn + bg * 16 + b_nrow) * ROW_B + ks * 32 + b_j * 16);
                uint32_t bh0, bh1, bh2, bh3, bl0, bl1, bl2, bl3;
                ldsm_x4(bh0, bh1, bh2, bh3, bHi + off);
                ldsm_x4(bl0, bl1, bl2, bl3, bLo + off);
#pragma unroll
                for (int mi = 0; mi < 2; mi++) {
                    mma_bf16(acc[mi][bg * 2 + 0], ah + mi * 4, bh0, bh1);
                    mma_bf16(acc[mi][bg * 2 + 0], ah + mi * 4, bl0, bl1);
                    mma_bf16(acc[mi][bg * 2 + 0], al + mi * 4, bh0, bh1);
                    mma_bf16(acc[mi][bg * 2 + 1], ah + mi * 4, bh2, bh3);
                    mma_bf16(acc[mi][bg * 2 + 1], ah + mi * 4, bl2, bl3);
                    mma_bf16(acc[mi][bg * 2 + 1], al + mi * 4, bh2, bh3);
                }
            }
        }
        __syncthreads();
    }

    const int rbase = row0 + wm + (lane >> 2);
    const int cbase = wn + (lane & 3) * 2;
#pragma unroll
    for (int mi = 0; mi < 2; mi++) {
#pragma unroll
        for (int ni = 0; ni < 8; ni++) {
            int col = cbase + ni * 8;
            int r1 = rbase + mi * 16, r2 = r1 + 8;
            if (r1 < M) *(float2*)(out + (size_t)r1 * CC + col) =
                make_float2(acc[mi][ni][0], acc[mi][ni][1]);
            if (r2 < M) *(float2*)(out + (size_t)r2 * CC + col) =
                make_float2(acc[mi][ni][2], acc[mi][ni][3]);
        }
    }
}

// ---------------------------------------------------------------------------
// Final GEMM: out = [A0|A1] (rows [rowBase,..) x 256) @ Wt^T + bias
__global__ __launch_bounds__(256, 2) void gemm_mma_kernel(
    const float* __restrict__ A0, const float* __restrict__ A1,
    const __nv_bfloat16* __restrict__ wh, const __nv_bfloat16* __restrict__ wl,
    const float* __restrict__ bias,
    float* __restrict__ out, int rowBase, int M) {

    __shared__ __align__(16) char sA_hi[128 * ROW_B];
    __shared__ __align__(16) char sA_lo[128 * ROW_B];
    __shared__ __align__(16) char sB_hi[128 * ROW_B];
    __shared__ __align__(16) char sB_lo[128 * ROW_B];

    const int tid = threadIdx.x;
    const int lane = tid & 31;
    const int wid = tid >> 5;
    const int wm = (wid & 3) * 32;
    const int wn = (wid >> 2) * 64;
    const int row0 = rowBase + blockIdx.x * 128;

    float acc[2][8][4] = {};

    const uint32_t aHi = smem_u32(sA_hi), aLo = smem_u32(sA_lo);
    const uint32_t bHi = smem_u32(sB_hi), bLo = smem_u32(sB_lo);

    const int a_mrow = ((lane >> 3) & 1) * 8 + (lane & 7);
    const int a_j = lane >> 4;
    const int b_nrow = (lane >> 4) * 8 + (lane & 7);
    const int b_j = (lane >> 3) & 1;

    float4 vA[4];

    auto loadA = [&](int c) {
        const float* SA = (c < 4) ? A0 : A1;
        const int koff = (c & 3) * 32;
#pragma unroll
        for (int i = 0; i < 4; i++) {
            int idx = tid + (i << 8);
            int m = idx >> 3, k4 = idx & 7;
            int row = row0 + m;
            vA[i] = (row < M) ? *(const float4*)(SA + (size_t)row * CC + koff + (k4 << 2))
                              : make_float4(0.f, 0.f, 0.f, 0.f);
        }
    };

    loadA(0);

    for (int c = 0; c < 8; c++) {
#pragma unroll
        for (int i = 0; i < 2; i++) {
            int idx = tid + (i << 8);
            int n = idx >> 2, j = idx & 3;
            size_t srcOff = (size_t)n * 512 + (size_t)c * 64 + (size_t)j * 16;
            cp_async16(bHi + n * ROW_B + (j << 4), (const char*)wh + srcOff);
            cp_async16(bLo + n * ROW_B + (j << 4), (const char*)wl + srcOff);
        }
        asm volatile("cp.async.commit_group;" ::: "memory");

#pragma unroll
        for (int i = 0; i < 4; i++) {
            int idx = tid + (i << 8);
            int m = idx >> 3, k4 = idx & 7;
            float x0 = vA[i].x, x1 = vA[i].y, x2 = vA[i].z, x3 = vA[i].w;
            __nv_bfloat162 h01 = make_bfloat162(__float2bfloat16(x0), __float2bfloat16(x1));
            __nv_bfloat162 h23 = make_bfloat162(__float2bfloat16(x2), __float2bfloat16(x3));
            __nv_bfloat162 l01 = make_bfloat162(
                __float2bfloat16(x0 - __bfloat162float(h01.x)),
                __float2bfloat16(x1 - __bfloat162float(h01.y)));
            __nv_bfloat162 l23 = make_bfloat162(
                __float2bfloat16(x2 - __bfloat162float(h23.x)),
                __float2bfloat16(x3 - __bfloat162float(h23.y)));
            char* pd = sA_hi + m * ROW_B + (k4 << 3);
            *(__nv_bfloat162*)(pd + 0) = h01;
            *(__nv_bfloat162*)(pd + 4) = h23;
            char* pl = sA_lo + m * ROW_B + (k4 << 3);
            *(__nv_bfloat162*)(pl + 0) = l01;
            *(__nv_bfloat162*)(pl + 4) = l23;
        }

        if (c < 7) loadA(c + 1);

        asm volatile("cp.async.wait_group 0;" ::: "memory");
        __syncthreads();

#pragma unroll
        for (int ks = 0; ks < 2; ks++) {
            uint32_t ah[8], al[8];
#pragma unroll
            for (int mi = 0; mi < 2; mi++) {
                uint32_t off = (uint32_t)((wm + mi * 16 + a_mrow) * ROW_B + ks * 32 + a_j * 16);
                ldsm_x4(ah[mi * 4 + 0], ah[mi * 4 + 1], ah[mi * 4 + 2], ah[mi * 4 + 3], aHi + off);
                ldsm_x4(al[mi * 4 + 0], al[mi * 4 + 1], al[mi * 4 + 2], al[mi * 4 + 3], aLo + off);
            }
#pragma unroll
            for (int bg = 0; bg < 4; bg++) {
                uint32_t off = (uint32_t)((wn + bg * 16 + b_nrow) * ROW_B + ks * 32 + b_j * 16);
                uint32_t bh0, bh1, bh2, bh3, bl0, bl1, bl2, bl3;
                ldsm_x4(bh0, bh1, bh2, bh3, bHi + off);
                ldsm_x4(bl0, bl1, bl2, bl3, bLo + off);
#pragma unroll
                for (int mi = 0; mi < 2; mi++) {
                    mma_bf16(acc[mi][bg * 2 + 0], ah + mi * 4, bh0, bh1);
                    mma_bf16(acc[mi][bg * 2 + 0], ah + mi * 4, bl0, bl1);
                    mma_bf16(acc[mi][bg * 2 + 0], al + mi * 4, bh0, bh1);
                    mma_bf16(acc[mi][bg * 2 + 1], ah + mi * 4, bh2, bh3);
                    mma_bf16(acc[mi][bg * 2 + 1], ah + mi * 4, bl2, bl3);
                    mma_bf16(acc[mi][bg * 2 + 1], al + mi * 4, bh2, bh3);
                }
            }
        }
        __syncthreads();
    }

    const int rbase = row0 + wm + (lane >> 2);
    const int cbase = wn + (lane & 3) * 2;
#pragma unroll
    for (int mi = 0; mi < 2; mi++) {
#pragma unroll
        for (int ni = 0; ni < 8; ni++) {
            int col = cbase + ni * 8;
            float b0 = __ldg(bias + col), b1 = __ldg(bias + col + 1);
            int r1 = rbase + mi * 16, r2 = r1 + 8;
            if (r1 < M) *(float2*)(out + (size_t)r1 * CC + col) =
                make_float2(acc[mi][ni][0] + b0, acc[mi][ni][1] + b1);
            if (r2 < M) *(float2*)(out + (size_t)r2 * CC + col) =
                make_float2(acc[mi][ni][2] + b0, acc[mi][ni][3] + b1);
        }
    }
}

// ---------------------------------------------------------------------------
extern "C" void kernel_launch(void* const* d_in, const int* in_sizes, int n_in,
                              void* d_out, int out_size) {
    const float* x     = (const float*)d_in[0];
    const int*   ei    = (const int*)d_in[1];     // int32
    const float* W1_l  = (const float*)d_in[2];
    const float* b1_l  = (const float*)d_in[3];
    const float* W1_r  = (const float*)d_in[4];
    const float* W2_l  = (const float*)d_in[5];
    const float* b2_l  = (const float*)d_in[6];
    const float* W2_r  = (const float*)d_in[7];
    const float* W_lin = (const float*)d_in[8];
    const float* b_lin = (const float*)d_in[9];
    float* out = (float*)d_out;

    const int M = in_sizes[0] / CC;      // 50000
    const int E = in_sizes[1] / 2;       // 600000

    float *x1, *x2, *yl, *yr, *yl2, *yr2;
    int *cnt, *rs, *cur, *csr, *part;
    __nv_bfloat16 *wbh, *wbl;
    cudaGetSymbolAddress((void**)&x1, g_x1);
    cudaGetSymbolAddress((void**)&x2, g_x2);
    cudaGetSymbolAddress((void**)&yl, g_yl);
    cudaGetSymbolAddress((void**)&yr, g_yr);
    cudaGetSymbolAddress((void**)&yl2, g_yl2);
    cudaGetSymbolAddress((void**)&yr2, g_yr2);
    cudaGetSymbolAddress((void**)&cnt, g_cnt);
    cudaGetSymbolAddress((void**)&rs, g_rs);
    cudaGetSymbolAddress((void**)&cur, g_cur);
    cudaGetSymbolAddress((void**)&csr, g_csr);
    cudaGetSymbolAddress((void**)&part, g_part);
    cudaGetSymbolAddress((void**)&wbh, g_wbh);
    cudaGetSymbolAddress((void**)&wbl, g_wbl);

    // side stream + events (created once, on the un-captured correctness call)
    static cudaStream_t s2 = nullptr;
    static cudaEvent_t evF = nullptr, evCSR = nullptr, evA = nullptr, evB = nullptr,
                       evC = nullptr, evD = nullptr;
    if (!s2) {
        cudaStreamCreateWithFlags(&s2, cudaStreamNonBlocking);
        cudaEventCreateWithFlags(&evF, cudaEventDisableTiming);
        cudaEventCreateWithFlags(&evCSR, cudaEventDisableTiming);
        cudaEventCreateWithFlags(&evA, cudaEventDisableTiming);
        cudaEventCreateWithFlags(&evB, cudaEventDisableTiming);
        cudaEventCreateWithFlags(&evC, cudaEventDisableTiming);
        cudaEventCreateWithFlags(&evD, cudaEventDisableTiming);
    }

    const int TB = 256;
    const int edgeBlocks = (E + TB - 1) / TB;
    const int nScanBlk = (M + 511) / 512;            // 98

    // split-half geometry
    const int H = 25088;                             // 196 * 128
    const int M1 = M - H;                            // 24912
    const int gB0 = H / 128;                         // 196
    const int gB1 = (M1 + 127) / 128;                // 195
    const int cB0 = (H * 32 + TB - 1) / TB;          // 3136
    const int cB1 = (M1 * 32 + TB - 1) / TB;         // 3114
    const int gemmBlocksAll = (M + 127) / 128;       // 391

    // ---- fork: CSR build on s2; prep + transform-GEMM1 on main ----
    cudaEventRecord(evF, 0);
    cudaStreamWaitEvent(s2, evF, 0);

    cudaMemsetAsync(cnt, 0, (size_t)M * sizeof(int), s2);
    count_kernel<<<edgeBlocks, TB, 0, s2>>>(ei, cnt, E);
    scan_local_kernel<<<nScanBlk, 512, 0, s2>>>(cnt, rs, part, M);
    scan_add_kernel<<<nScanBlk, 512, 0, s2>>>(rs, part, cur, M, nScanBlk);
    fill_kernel<<<edgeBlocks, TB, 0, s2>>>(ei, cur, csr, E);
    cudaEventRecord(evCSR, s2);

    prep_w_kernel<<<384, TB>>>(W1_l, W1_r, W2_l, W2_r, W_lin, W_lin + 128 * CC, wbh, wbl);
    gemm_t_kernel<<<dim3(gemmBlocksAll, 2), TB>>>(x, wbh, wbl, yl, yr, 0, M);   // Y1

    cudaStreamWaitEvent(0, evCSR, 0);

    // ---- layer 1 combine (reads yl/yr), pipelined with gemmT2 (writes yl2/yr2) ----
    combine_kernel<<<cB0, TB>>>(yl, yr, csr, rs, cnt, b1_l, x1, 0, H);
    cudaEventRecord(evA, 0);
    cudaStreamWaitEvent(s2, evA, 0);
    combine_kernel<<<cB1, TB, 0, s2>>>(yl, yr, csr, rs, cnt, b1_l, x1, H, M1);
    cudaEventRecord(evB, s2);

    // gemmT2 half-0 only needs x1 rows [0,H) (combine1 half-0, main-ordered);
    // it writes yl2/yr2 — disjoint from combine1 half-1's reads of yl/yr.
    gemm_t_kernel<<<dim3(gB0, 2), TB>>>(x1, wbh + 32768, wbl + 32768, yl2, yr2, 0, M);
    cudaStreamWaitEvent(0, evB, 0);
    gemm_t_kernel<<<dim3(gB1, 2), TB>>>(x1, wbh + 32768, wbl + 32768, yl2, yr2, H, M);

    // ---- layer 2 combine (reads yl2/yr2), pipelined with final gemm ----
    combine_kernel<<<cB0, TB>>>(yl2, yr2, csr, rs, cnt, b2_l, x2, 0, H);
    cudaEventRecord(evC, 0);
    cudaStreamWaitEvent(s2, evC, 0);
    combine_kernel<<<cB1, TB, 0, s2>>>(yl2, yr2, csr, rs, cnt, b2_l, x2, H, M1);
    cudaEventRecord(evD, s2);

    // final gemm half-0 reads x1 (complete) + x2 rows [0,H) only; writes out rows [0,H).
    gemm_mma_kernel<<<gB0, TB>>>(x1, x2, wbh + 65536, wbl + 65536, b_lin, out, 0, M);
    cudaStreamWaitEvent(0, evD, 0);
    gemm_mma_kernel<<<gB1, TB>>>(x1, x2, wbh + 65536, wbl + 65536, b_lin, out, H, M);
}

// round 16
// speedup vs baseline: 1.0955x; 1.0955x over previous
#include <cuda_runtime.h>
#include <cuda_bf16.h>
#include <cstdint>

#define NN 50000
#define CC 128
#define EE 600000

// Scratch (device globals; no cudaMalloc allowed)
__device__ float g_x1[NN * CC];
__device__ float g_x2[NN * CC];
__device__ float g_yl[NN * CC];
__device__ float g_yr[NN * CC];
__device__ int   g_cnt[NN];
__device__ int   g_rs[NN];
__device__ int   g_cur[NN];
__device__ int   g_csr[EE];
__device__ int   g_part[128];
// Pre-transposed bf16 hi/lo weights: [gemm(3)][n(128)][k(256)]
__device__ __nv_bfloat16 g_wbh[3 * 128 * 256];
__device__ __nv_bfloat16 g_wbl[3 * 128 * 256];

// ---------------------------------------------------------------------------
__device__ __forceinline__ uint32_t smem_u32(const void* p) {
    uint32_t a;
    asm("{ .reg .u64 t; cvta.to.shared.u64 t, %1; cvt.u32.u64 %0, t; }" : "=r"(a) : "l"(p));
    return a;
}
__device__ __forceinline__ void ldsm_x4(uint32_t& r0, uint32_t& r1, uint32_t& r2, uint32_t& r3,
                                        uint32_t addr) {
    asm volatile("ldmatrix.sync.aligned.m8n8.x4.shared.b16 {%0,%1,%2,%3}, [%4];"
                 : "=r"(r0), "=r"(r1), "=r"(r2), "=r"(r3) : "r"(addr));
}
__device__ __forceinline__ void mma_bf16(float* d, const uint32_t* a, uint32_t b0, uint32_t b1) {
    asm volatile(
        "mma.sync.aligned.m16n8k16.row.col.f32.bf16.bf16.f32 "
        "{%0,%1,%2,%3}, {%4,%5,%6,%7}, {%8,%9}, {%0,%1,%2,%3};"
        : "+f"(d[0]), "+f"(d[1]), "+f"(d[2]), "+f"(d[3])
        : "r"(a[0]), "r"(a[1]), "r"(a[2]), "r"(a[3]), "r"(b0), "r"(b1));
}
__device__ __forceinline__ void cp_async16(uint32_t dst, const void* src) {
    asm volatile("cp.async.cg.shared.global [%0], [%1], 16;" :: "r"(dst), "l"(src) : "memory");
}

// ---------------------------------------------------------------------------
// CSR build
__global__ void count_kernel(const int* __restrict__ ei, int* __restrict__ cnt, int E) {
    int i = blockIdx.x * blockDim.x + threadIdx.x;
    if (i < E) atomicAdd(&cnt[ei[E + i]], 1);
}

__global__ void scan_local_kernel(const int* __restrict__ cnt, int* __restrict__ rs,
                                  int* __restrict__ part, int n) {
    __shared__ int sh[512];
    int t = threadIdx.x;
    int i = blockIdx.x * 512 + t;
    int v = (i < n) ? cnt[i] : 0;
    sh[t] = v;
    __syncthreads();
#pragma unroll
    for (int off = 1; off < 512; off <<= 1) {
        int add = (t >= off) ? sh[t - off] : 0;
        __syncthreads();
        sh[t] += add;
        __syncthreads();
    }
    if (i < n) rs[i] = sh[t] - v;
    if (t == 511) part[blockIdx.x] = sh[511];
}

// every block re-scans the (<=128) partials in smem, then applies its offset
__global__ void scan_add_kernel(int* __restrict__ rs, const int* __restrict__ part,
                                int* __restrict__ cur, int n, int nb) {
    __shared__ int sh[128];
    int t = threadIdx.x;
    if (t < 128) sh[t] = (t < nb) ? part[t] : 0;
    __syncthreads();
#pragma unroll
    for (int off = 1; off < 128; off <<= 1) {
        int add = (t >= off && t < 128) ? sh[t - off] : 0;
        __syncthreads();
        if (t < 128) sh[t] += add;
        __syncthreads();
    }
    int boff = (blockIdx.x > 0) ? sh[blockIdx.x - 1] : 0;
    int i = blockIdx.x * 512 + t;
    if (i < n) {
        int v = rs[i] + boff;
        rs[i] = v;
        cur[i] = v;
    }
}

__global__ void fill_kernel(const int* __restrict__ ei, int* __restrict__ cur,
                            int* __restrict__ csr, int E) {
    int i = blockIdx.x * blockDim.x + threadIdx.x;
    if (i < E) {
        int slot = atomicAdd(&cur[ei[E + i]], 1);
        csr[slot] = ei[i];
    }
}

// ---------------------------------------------------------------------------
// combine: x_out[w] = relu(mean_agg(Y_l)[w] + Y_rb[w])   (bias pre-folded into yr)
__global__ __launch_bounds__(256) void combine_kernel(
    const float* __restrict__ yl, const float* __restrict__ yr,
    const int* __restrict__ csr, const int* __restrict__ rs,
    const int* __restrict__ cnt,
    float* __restrict__ out, int N) {
    int w = (blockIdx.x * blockDim.x + threadIdx.x) >> 5;
    if (w >= N) return;
    const int lane = threadIdx.x & 31;
    const int start = rs[w];
    const int deg = cnt[w];
    const int* nb = csr + start;

    float4 acc = make_float4(0.f, 0.f, 0.f, 0.f);
    int j = 0;
    for (; j + 4 <= deg; j += 4) {
        int s0 = __ldg(nb + j), s1 = __ldg(nb + j + 1);
        int s2 = __ldg(nb + j + 2), s3 = __ldg(nb + j + 3);
        float4 v0 = __ldg((const float4*)(yl + (size_t)s0 * CC) + lane);
        float4 v1 = __ldg((const float4*)(yl + (size_t)s1 * CC) + lane);
        float4 v2 = __ldg((const float4*)(yl + (size_t)s2 * CC) + lane);
        float4 v3 = __ldg((const float4*)(yl + (size_t)s3 * CC) + lane);
        acc.x += v0.x + v1.x + v2.x + v3.x;
        acc.y += v0.y + v1.y + v2.y + v3.y;
        acc.z += v0.z + v1.z + v2.z + v3.z;
        acc.w += v0.w + v1.w + v2.w + v3.w;
    }
    for (; j < deg; j++) {
        int s0 = __ldg(nb + j);
        float4 v0 = __ldg((const float4*)(yl + (size_t)s0 * CC) + lane);
        acc.x += v0.x; acc.y += v0.y; acc.z += v0.z; acc.w += v0.w;
    }
    float inv = 1.0f / (float)(deg > 0 ? deg : 1);
    float4 r = __ldg((const float4*)(yr + (size_t)w * CC) + lane);
    float4 o;
    o.x = fmaxf(acc.x * inv + r.x, 0.f);
    o.y = fmaxf(acc.y * inv + r.y, 0.f);
    o.z = fmaxf(acc.z * inv + r.z, 0.f);
    o.w = fmaxf(acc.w * inv + r.w, 0.f);
    ((float4*)(out + (size_t)w * CC))[lane] = o;
}

// ---------------------------------------------------------------------------
// Weight prep for a subset of gemms: gFirst..gFirst+nG-1.
// W[k][n] (row-major, 2x 128x128 stacked in k) -> Wt[n][k] bf16 hi/lo
__global__ void prep_w_kernel(const float* wl0, const float* wr0,
                              const float* wl1, const float* wr1,
                              __nv_bfloat16* wh, __nv_bfloat16* wl,
                              int gFirst, int nG) {
    int gid = blockIdx.x * blockDim.x + threadIdx.x;   // [gLocal][n][k]
    if (gid >= nG * 128 * 256) return;
    int gl = gid >> 15;
    int rem = gid & 32767;
    int n = rem >> 8;
    int k = rem & 255;
    const float* W;
    if (gl == 0) W = (k < 128) ? wl0 : wr0;
    else         W = (k < 128) ? wl1 : wr1;
    float v = W[(size_t)(k & 127) * CC + n];
    __nv_bfloat16 h = __float2bfloat16(v);
    __nv_bfloat16 l = __float2bfloat16(v - __bfloat162float(h));
    int g = gFirst + gl;
    int dst = (g << 15) + (n << 8) + k;
    wh[dst] = h;
    wl[dst] = l;
}

// ---------------------------------------------------------------------------
#define ROW_B 80

// Transform GEMM: Y_half = X (Mx128) @ Wt[half]^T, half = blockIdx.y.
// yr half gets bias added in the epilogue (bias==nullptr -> none).
__global__ __launch_bounds__(256, 2) void gemm_t_kernel(
    const float* __restrict__ X,
    const __nv_bfloat16* __restrict__ wh, const __nv_bfloat16* __restrict__ wl,
    const float* __restrict__ bias,
    float* __restrict__ yl, float* __restrict__ yr, int M) {

    __shared__ __align__(16) char sA_hi[128 * ROW_B];
    __shared__ __align__(16) char sA_lo[128 * ROW_B];
    __shared__ __align__(16) char sB_hi[128 * ROW_B];
    __shared__ __align__(16) char sB_lo[128 * ROW_B];

    const int tid = threadIdx.x;
    const int lane = tid & 31;
    const int wid = tid >> 5;
    const int wm = (wid & 3) * 32;
    const int wn = (wid >> 2) * 64;
    const int row0 = blockIdx.x * 128;
    const int half = blockIdx.y;
    float* out = half ? yr : yl;

    float acc[2][8][4] = {};

    const uint32_t aHi = smem_u32(sA_hi), aLo = smem_u32(sA_lo);
    const uint32_t bHi = smem_u32(sB_hi), bLo = smem_u32(sB_lo);

    const int a_mrow = ((lane >> 3) & 1) * 8 + (lane & 7);
    const int a_j = lane >> 4;
    const int b_nrow = (lane >> 4) * 8 + (lane & 7);
    const int b_j = (lane >> 3) & 1;

    float4 vA[4];

    auto loadA = [&](int c) {
        const int koff = c * 32;
#pragma unroll
        for (int i = 0; i < 4; i++) {
            int idx = tid + (i << 8);
            int m = idx >> 3, k4 = idx & 7;
            int row = row0 + m;
            vA[i] = (row < M) ? *(const float4*)(X + (size_t)row * CC + koff + (k4 << 2))
                              : make_float4(0.f, 0.f, 0.f, 0.f);
        }
    };

    loadA(0);

    for (int c = 0; c < 4; c++) {
        const int cb = half * 4 + c;
#pragma unroll
        for (int i = 0; i < 2; i++) {
            int idx = tid + (i << 8);
            int n = idx >> 2, j = idx & 3;
            size_t srcOff = (size_t)n * 512 + (size_t)cb * 64 + (size_t)j * 16;
            cp_async16(bHi + n * ROW_B + (j << 4), (const char*)wh + srcOff);
            cp_async16(bLo + n * ROW_B + (j << 4), (const char*)wl + srcOff);
        }
        asm volatile("cp.async.commit_group;" ::: "memory");

#pragma unroll
        for (int i = 0; i < 4; i++) {
            int idx = tid + (i << 8);
            int m = idx >> 3, k4 = idx & 7;
            float x0 = vA[i].x, x1 = vA[i].y, x2 = vA[i].z, x3 = vA[i].w;
            __nv_bfloat162 h01 = make_bfloat162(__float2bfloat16(x0), __float2bfloat16(x1));
            __nv_bfloat162 h23 = make_bfloat162(__float2bfloat16(x2), __float2bfloat16(x3));
            __nv_bfloat162 l01 = make_bfloat162(
                __float2bfloat16(x0 - __bfloat162float(h01.x)),
                __float2bfloat16(x1 - __bfloat162float(h01.y)));
            __nv_bfloat162 l23 = make_bfloat162(
                __float2bfloat16(x2 - __bfloat162float(h23.x)),
                __float2bfloat16(x3 - __bfloat162float(h23.y)));
            char* pd = sA_hi + m * ROW_B + (k4 << 3);
            *(__nv_bfloat162*)(pd + 0) = h01;
            *(__nv_bfloat162*)(pd + 4) = h23;
            char* pl = sA_lo + m * ROW_B + (k4 << 3);
            *(__nv_bfloat162*)(pl + 0) = l01;
            *(__nv_bfloat162*)(pl + 4) = l23;
        }

        if (c < 3) loadA(c + 1);

        asm volatile("cp.async.wait_group 0;" ::: "memory");
        __syncthreads();

#pragma unroll
        for (int ks = 0; ks < 2; ks++) {
            uint32_t ah[8], al[8];
#pragma unroll
            for (int mi = 0; mi < 2; mi++) {
                uint32_t off = (uint32_t)((wm + mi * 16 + a_mrow) * ROW_B + ks * 32 + a_j * 16);
                ldsm_x4(ah[mi * 4 + 0], ah[mi * 4 + 1], ah[mi * 4 + 2], ah[mi * 4 + 3], aHi + off);
                ldsm_x4(al[mi * 4 + 0], al[mi * 4 + 1], al[mi * 4 + 2], al[mi * 4 + 3], aLo + off);
            }
#pragma unroll
            for (int bg = 0; bg < 4; bg++) {
                uint32_t off = (uint32_t)((wn + bg * 16 + b_nrow) * ROW_B + ks * 32 + b_j * 16);
                uint32_t bh0, bh1, bh2, bh3, bl0, bl1, bl2, bl3;
                ldsm_x4(bh0, bh1, bh2, bh3, bHi + off);
                ldsm_x4(bl0, bl1, bl2, bl3, bLo + off);
#pragma unroll
                for (int mi = 0; mi < 2; mi++) {
                    mma_bf16(acc[mi][bg * 2 + 0], ah + mi * 4, bh0, bh1);
                    mma_bf16(acc[mi][bg * 2 + 0], ah + mi * 4, bl0, bl1);
                    mma_bf16(acc[mi][bg * 2 + 0], al + mi * 4, bh0, bh1);
                    mma_bf16(acc[mi][bg * 2 + 1], ah + mi * 4, bh2, bh3);
                    mma_bf16(acc[mi][bg * 2 + 1], ah + mi * 4, bl2, bl3);
                    mma_bf16(acc[mi][bg * 2 + 1], al + mi * 4, bh2, bh3);
                }
            }
        }
        __syncthreads();
    }

    const int rbase = row0 + wm + (lane >> 2);
    const int cbase = wn + (lane & 3) * 2;
    const bool addB = (half == 1) && (bias != nullptr);
#pragma unroll
    for (int mi = 0; mi < 2; mi++) {
#pragma unroll
        for (int ni = 0; ni < 8; ni++) {
            int col = cbase + ni * 8;
            float b0 = addB ? __ldg(bias + col) : 0.f;
            float b1 = addB ? __ldg(bias + col + 1) : 0.f;
            int r1 = rbase + mi * 16, r2 = r1 + 8;
            if (r1 < M) *(float2*)(out + (size_t)r1 * CC + col) =
                make_float2(acc[mi][ni][0] + b0, acc[mi][ni][1] + b1);
            if (r2 < M) *(float2*)(out + (size_t)r2 * CC + col) =
                make_float2(acc[mi][ni][2] + b0, acc[mi][ni][3] + b1);
        }
    }
}

// ---------------------------------------------------------------------------
// Final GEMM: out = [A0|A1] (Mx256) @ Wt^T + bias
__global__ __launch_bounds__(256, 2) void gemm_mma_kernel(
    const float* __restrict__ A0, const float* __restrict__ A1,
    const __nv_bfloat16* __restrict__ wh, const __nv_bfloat16* __restrict__ wl,
    const float* __restrict__ bias,
    float* __restrict__ out, int M) {

    __shared__ __align__(16) char sA_hi[128 * ROW_B];
    __shared__ __align__(16) char sA_lo[128 * ROW_B];
    __shared__ __align__(16) char sB_hi[128 * ROW_B];
    __shared__ __align__(16) char sB_lo[128 * ROW_B];

    const int tid = threadIdx.x;
    const int lane = tid & 31;
    const int wid = tid >> 5;
    const int wm = (wid & 3) * 32;
    const int wn = (wid >> 2) * 64;
    const int row0 = blockIdx.x * 128;

    float acc[2][8][4] = {};

    const uint32_t aHi = smem_u32(sA_hi), aLo = smem_u32(sA_lo);
    const uint32_t bHi = smem_u32(sB_hi), bLo = smem_u32(sB_lo);

    const int a_mrow = ((lane >> 3) & 1) * 8 + (lane & 7);
    const int a_j = lane >> 4;
    const int b_nrow = (lane >> 4) * 8 + (lane & 7);
    const int b_j = (lane >> 3) & 1;

    float4 vA[4];

    auto loadA = [&](int c) {
        const float* SA = (c < 4) ? A0 : A1;
        const int koff = (c & 3) * 32;
#pragma unroll
        for (int i = 0; i < 4; i++) {
            int idx = tid + (i << 8);
            int m = idx >> 3, k4 = idx & 7;
            int row = row0 + m;
            vA[i] = (row < M) ? *(const float4*)(SA + (size_t)row * CC + koff + (k4 << 2))
                              : make_float4(0.f, 0.f, 0.f, 0.f);
        }
    };

    loadA(0);

    for (int c = 0; c < 8; c++) {
#pragma unroll
        for (int i = 0; i < 2; i++) {
            int idx = tid + (i << 8);
            int n = idx >> 2, j = idx & 3;
            size_t srcOff = (size_t)n * 512 + (size_t)c * 64 + (size_t)j * 16;
            cp_async16(bHi + n * ROW_B + (j << 4), (const char*)wh + srcOff);
            cp_async16(bLo + n * ROW_B + (j << 4), (const char*)wl + srcOff);
        }
        asm volatile("cp.async.commit_group;" ::: "memory");

#pragma unroll
        for (int i = 0; i < 4; i++) {
            int idx = tid + (i << 8);
            int m = idx >> 3, k4 = idx & 7;
            float x0 = vA[i].x, x1 = vA[i].y, x2 = vA[i].z, x3 = vA[i].w;
            __nv_bfloat162 h01 = make_bfloat162(__float2bfloat16(x0), __float2bfloat16(x1));
            __nv_bfloat162 h23 = make_bfloat162(__float2bfloat16(x2), __float2bfloat16(x3));
            __nv_bfloat162 l01 = make_bfloat162(
                __float2bfloat16(x0 - __bfloat162float(h01.x)),
                __float2bfloat16(x1 - __bfloat162float(h01.y)));
            __nv_bfloat162 l23 = make_bfloat162(
                __float2bfloat16(x2 - __bfloat162float(h23.x)),
                __float2bfloat16(x3 - __bfloat162float(h23.y)));
            char* pd = sA_hi + m * ROW_B + (k4 << 3);
            *(__nv_bfloat162*)(pd + 0) = h01;
            *(__nv_bfloat162*)(pd + 4) = h23;
            char* pl = sA_lo + m * ROW_B + (k4 << 3);
            *(__nv_bfloat162*)(pl + 0) = l01;
            *(__nv_bfloat162*)(pl + 4) = l23;
        }

        if (c < 7) loadA(c + 1);

        asm volatile("cp.async.wait_group 0;" ::: "memory");
        __syncthreads();

#pragma unroll
        for (int ks = 0; ks < 2; ks++) {
            uint32_t ah[8], al[8];
#pragma unroll
            for (int mi = 0; mi < 2; mi++) {
                uint32_t off = (uint32_t)((wm + mi * 16 + a_mrow) * ROW_B + ks * 32 + a_j * 16);
                ldsm_x4(ah[mi * 4 + 0], ah[mi * 4 + 1], ah[mi * 4 + 2], ah[mi * 4 + 3], aHi + off);
                ldsm_x4(al[mi * 4 + 0], al[mi * 4 + 1], al[mi * 4 + 2], al[mi * 4 + 3], aLo + off);
            }
#pragma unroll
            for (int bg = 0; bg < 4; bg++) {
                uint32_t off = (uint32_t)((wn + bg * 16 + b_nrow) * ROW_B + ks * 32 + b_j * 16);
                uint32_t bh0, bh1, bh2, bh3, bl0, bl1, bl2, bl3;
                ldsm_x4(bh0, bh1, bh2, bh3, bHi + off);
                ldsm_x4(bl0, bl1, bl2, bl3, bLo + off);
#pragma unroll
                for (int mi = 0; mi < 2; mi++) {
                    mma_bf16(acc[mi][bg * 2 + 0], ah + mi * 4, bh0, bh1);
                    mma_bf16(acc[mi][bg * 2 + 0], ah + mi * 4, bl0, bl1);
                    mma_bf16(acc[mi][bg * 2 + 0], al + mi * 4, bh0, bh1);
                    mma_bf16(acc[mi][bg * 2 + 1], ah + mi * 4, bh2, bh3);
                    mma_bf16(acc[mi][bg * 2 + 1], ah + mi * 4, bl2, bl3);
                    mma_bf16(acc[mi][bg * 2 + 1], al + mi * 4, bh2, bh3);
                }
            }
        }
        __syncthreads();
    }

    const int rbase = row0 + wm + (lane >> 2);
    const int cbase = wn + (lane & 3) * 2;
#pragma unroll
    for (int mi = 0; mi < 2; mi++) {
#pragma unroll
        for (int ni = 0; ni < 8; ni++) {
            int col = cbase + ni * 8;
            float b0 = __ldg(bias + col), b1 = __ldg(bias + col + 1);
            int r1 = rbase + mi * 16, r2 = r1 + 8;
            if (r1 < M) *(float2*)(out + (size_t)r1 * CC + col) =
                make_float2(acc[mi][ni][0] + b0, acc[mi][ni][1] + b1);
            if (r2 < M) *(float2*)(out + (size_t)r2 * CC + col) =
                make_float2(acc[mi][ni][2] + b0, acc[mi][ni][3] + b1);
        }
    }
}

// ---------------------------------------------------------------------------
extern "C" void kernel_launch(void* const* d_in, const int* in_sizes, int n_in,
                              void* d_out, int out_size) {
    const float* x     = (const float*)d_in[0];
    const int*   ei    = (const int*)d_in[1];     // int32
    const float* W1_l  = (const float*)d_in[2];
    const float* b1_l  = (const float*)d_in[3];
    const float* W1_r  = (const float*)d_in[4];
    const float* W2_l  = (const float*)d_in[5];
    const float* b2_l  = (const float*)d_in[6];
    const float* W2_r  = (const float*)d_in[7];
    const float* W_lin = (const float*)d_in[8];
    const float* b_lin = (const float*)d_in[9];
    float* out = (float*)d_out;

    const int M = in_sizes[0] / CC;      // 50000
    const int E = in_sizes[1] / 2;       // 600000

    float *x1, *x2, *yl, *yr;
    int *cnt, *rs, *cur, *csr, *part;
    __nv_bfloat16 *wbh, *wbl;
    cudaGetSymbolAddress((void**)&x1, g_x1);
    cudaGetSymbolAddress((void**)&x2, g_x2);
    cudaGetSymbolAddress((void**)&yl, g_yl);
    cudaGetSymbolAddress((void**)&yr, g_yr);
    cudaGetSymbolAddress((void**)&cnt, g_cnt);
    cudaGetSymbolAddress((void**)&rs, g_rs);
    cudaGetSymbolAddress((void**)&cur, g_cur);
    cudaGetSymbolAddress((void**)&csr, g_csr);
    cudaGetSymbolAddress((void**)&part, g_part);
    cudaGetSymbolAddress((void**)&wbh, g_wbh);
    cudaGetSymbolAddress((void**)&wbl, g_wbl);

    // side stream + events (created once, on the un-captured correctness call)
    static cudaStream_t s2 = nullptr;
    static cudaEvent_t evF = nullptr, evCSR = nullptr;
    if (!s2) {
        cudaStreamCreateWithFlags(&s2, cudaStreamNonBlocking);
        cudaEventCreateWithFlags(&evF, cudaEventDisableTiming);
        cudaEventCreateWithFlags(&evCSR, cudaEventDisableTiming);
    }

    const int TB = 256;
    const int gemmBlocks = (M + 127) / 128;          // 391
    const int combBlocks = (M * 32 + TB - 1) / TB;
    const int edgeBlocks = (E + TB - 1) / TB;
    const int nScanBlk = (M + 511) / 512;            // 98

    // ---- fork: prep(gemm1,2) + CSR build on s2; prep(gemm0) + gemmT1 on main ----
    cudaEventRecord(evF, 0);
    cudaStreamWaitEvent(s2, evF, 0);

    // s2: weights for layer-2 and final gemm, then the CSR pipeline
    prep_w_kernel<<<256, TB, 0, s2>>>(W2_l, W2_r, W_lin, W_lin + 128 * CC,
                                      wbh, wbl, 1, 2);
    cudaMemsetAsync(cnt, 0, (size_t)M * sizeof(int), s2);
    count_kernel<<<edgeBlocks, TB, 0, s2>>>(ei, cnt, E);
    scan_local_kernel<<<nScanBlk, 512, 0, s2>>>(cnt, rs, part, M);
    scan_add_kernel<<<nScanBlk, 512, 0, s2>>>(rs, part, cur, M, nScanBlk);
    fill_kernel<<<edgeBlocks, TB, 0, s2>>>(ei, cur, csr, E);
    cudaEventRecord(evCSR, s2);

    // main: layer-1 weights only, then transform-GEMM1 (bias b1 folded into yr)
    prep_w_kernel<<<128, TB>>>(W1_l, W1_r, nullptr, nullptr, wbh, wbl, 0, 1);
    gemm_t_kernel<<<dim3(gemmBlocks, 2), TB>>>(x, wbh, wbl, b1_l, yl, yr, M);

    cudaStreamWaitEvent(0, evCSR, 0);

    // ---- layer 1 combine: x1 = relu(mean_agg(Y1_l) + (Y1_r + b1)) ----
    combine_kernel<<<combBlocks, TB>>>(yl, yr, csr, rs, cnt, x1, M);

    // ---- layer 2 ----
    gemm_t_kernel<<<dim3(gemmBlocks, 2), TB>>>(x1, wbh + 32768, wbl + 32768, b2_l, yl, yr, M);
    combine_kernel<<<combBlocks, TB>>>(yl, yr, csr, rs, cnt, x2, M);

    // ---- final linear: [x1 | x2] @ W_lin + b_lin ----
    gemm_mma_kernel<<<gemmBlocks, TB>>>(x1, x2, wbh + 65536, wbl + 65536, b_lin, out, M);
}

// round 17
// speedup vs baseline: 1.1771x; 1.0745x over previous
#include <cuda_runtime.h>
#include <cuda_bf16.h>
#include <cuda_fp16.h>
#include <cstdint>

#define NN 50000
#define CC 128
#define EE 600000

// Scratch (device globals; no cudaMalloc allowed)
__device__ float  g_x1[NN * CC];
__device__ float  g_x2[NN * CC];
__device__ __half g_yl16[NN * CC];   // fp16 message tensor (halves gather traffic)
__device__ float  g_yr[NN * CC];
__device__ int    g_cnt[NN];
__device__ int    g_rs[NN];
__device__ int    g_cur[NN];
__device__ int    g_csr[EE];
__device__ int    g_part[128];
// Pre-transposed bf16 hi/lo weights: [gemm(3)][n(128)][k(256)]
__device__ __nv_bfloat16 g_wbh[3 * 128 * 256];
__device__ __nv_bfloat16 g_wbl[3 * 128 * 256];

// ---------------------------------------------------------------------------
__device__ __forceinline__ uint32_t smem_u32(const void* p) {
    uint32_t a;
    asm("{ .reg .u64 t; cvta.to.shared.u64 t, %1; cvt.u32.u64 %0, t; }" : "=r"(a) : "l"(p));
    return a;
}
__device__ __forceinline__ void ldsm_x4(uint32_t& r0, uint32_t& r1, uint32_t& r2, uint32_t& r3,
                                        uint32_t addr) {
    asm volatile("ldmatrix.sync.aligned.m8n8.x4.shared.b16 {%0,%1,%2,%3}, [%4];"
                 : "=r"(r0), "=r"(r1), "=r"(r2), "=r"(r3) : "r"(addr));
}
__device__ __forceinline__ void mma_bf16(float* d, const uint32_t* a, uint32_t b0, uint32_t b1) {
    asm volatile(
        "mma.sync.aligned.m16n8k16.row.col.f32.bf16.bf16.f32 "
        "{%0,%1,%2,%3}, {%4,%5,%6,%7}, {%8,%9}, {%0,%1,%2,%3};"
        : "+f"(d[0]), "+f"(d[1]), "+f"(d[2]), "+f"(d[3])
        : "r"(a[0]), "r"(a[1]), "r"(a[2]), "r"(a[3]), "r"(b0), "r"(b1));
}
__device__ __forceinline__ void cp_async16(uint32_t dst, const void* src) {
    asm volatile("cp.async.cg.shared.global [%0], [%1], 16;" :: "r"(dst), "l"(src) : "memory");
}

// ---------------------------------------------------------------------------
// CSR build
__global__ void count_kernel(const int* __restrict__ ei, int* __restrict__ cnt, int E) {
    int i = blockIdx.x * blockDim.x + threadIdx.x;
    if (i < E) atomicAdd(&cnt[ei[E + i]], 1);
}

__global__ void scan_local_kernel(const int* __restrict__ cnt, int* __restrict__ rs,
                                  int* __restrict__ part, int n) {
    __shared__ int sh[512];
    int t = threadIdx.x;
    int i = blockIdx.x * 512 + t;
    int v = (i < n) ? cnt[i] : 0;
    sh[t] = v;
    __syncthreads();
#pragma unroll
    for (int off = 1; off < 512; off <<= 1) {
        int add = (t >= off) ? sh[t - off] : 0;
        __syncthreads();
        sh[t] += add;
        __syncthreads();
    }
    if (i < n) rs[i] = sh[t] - v;
    if (t == 511) part[blockIdx.x] = sh[511];
}

__global__ void scan_add_kernel(int* __restrict__ rs, const int* __restrict__ part,
                                int* __restrict__ cur, int n, int nb) {
    __shared__ int sh[128];
    int t = threadIdx.x;
    if (t < 128) sh[t] = (t < nb) ? part[t] : 0;
    __syncthreads();
#pragma unroll
    for (int off = 1; off < 128; off <<= 1) {
        int add = (t >= off && t < 128) ? sh[t - off] : 0;
        __syncthreads();
        if (t < 128) sh[t] += add;
        __syncthreads();
    }
    int boff = (blockIdx.x > 0) ? sh[blockIdx.x - 1] : 0;
    int i = blockIdx.x * 512 + t;
    if (i < n) {
        int v = rs[i] + boff;
        rs[i] = v;
        cur[i] = v;
    }
}

__global__ void fill_kernel(const int* __restrict__ ei, int* __restrict__ cur,
                            int* __restrict__ csr, int E) {
    int i = blockIdx.x * blockDim.x + threadIdx.x;
    if (i < E) {
        int slot = atomicAdd(&cur[ei[E + i]], 1);
        csr[slot] = ei[i];
    }
}

// ---------------------------------------------------------------------------
// combine: x_out[w] = relu(mean_agg(Yl16)[w] + Yrb[w]) ; yl is fp16, yr fp32+bias
__global__ __launch_bounds__(256) void combine_kernel(
    const __half* __restrict__ yl16, const float* __restrict__ yr,
    const int* __restrict__ csr, const int* __restrict__ rs,
    const int* __restrict__ cnt,
    float* __restrict__ out, int N) {
    int w = (blockIdx.x * blockDim.x + threadIdx.x) >> 5;
    if (w >= N) return;
    const int lane = threadIdx.x & 31;
    const int start = rs[w];
    const int deg = cnt[w];
    const int* nb = csr + start;

    float4 acc = make_float4(0.f, 0.f, 0.f, 0.f);
    int j = 0;
    for (; j + 4 <= deg; j += 4) {
        int s0 = __ldg(nb + j), s1 = __ldg(nb + j + 1);
        int s2 = __ldg(nb + j + 2), s3 = __ldg(nb + j + 3);
        uint2 u0 = __ldg((const uint2*)(yl16 + (size_t)s0 * CC) + lane);
        uint2 u1 = __ldg((const uint2*)(yl16 + (size_t)s1 * CC) + lane);
        uint2 u2 = __ldg((const uint2*)(yl16 + (size_t)s2 * CC) + lane);
        uint2 u3 = __ldg((const uint2*)(yl16 + (size_t)s3 * CC) + lane);
#pragma unroll
        for (int q = 0; q < 4; q++) {
            uint2 u = (q == 0) ? u0 : (q == 1) ? u1 : (q == 2) ? u2 : u3;
            float2 a = __half22float2(*(__half2*)&u.x);
            float2 b = __half22float2(*(__half2*)&u.y);
            acc.x += a.x; acc.y += a.y; acc.z += b.x; acc.w += b.y;
        }
    }
    for (; j < deg; j++) {
        int s0 = __ldg(nb + j);
        uint2 u = __ldg((const uint2*)(yl16 + (size_t)s0 * CC) + lane);
        float2 a = __half22float2(*(__half2*)&u.x);
        float2 b = __half22float2(*(__half2*)&u.y);
        acc.x += a.x; acc.y += a.y; acc.z += b.x; acc.w += b.y;
    }
    float inv = 1.0f / (float)(deg > 0 ? deg : 1);
    float4 r = __ldg((const float4*)(yr + (size_t)w * CC) + lane);
    float4 o;
    o.x = fmaxf(acc.x * inv + r.x, 0.f);
    o.y = fmaxf(acc.y * inv + r.y, 0.f);
    o.z = fmaxf(acc.z * inv + r.z, 0.f);
    o.w = fmaxf(acc.w * inv + r.w, 0.f);
    ((float4*)(out + (size_t)w * CC))[lane] = o;
}

// ---------------------------------------------------------------------------
// Weight prep for gemms gFirst..gFirst+nG-1:
// W[k][n] (row-major, 2x 128x128 stacked in k) -> Wt[n][k] bf16 hi/lo
__global__ void prep_w_kernel(const float* wl0, const float* wr0,
                              const float* wl1, const float* wr1,
                              __nv_bfloat16* wh, __nv_bfloat16* wl,
                              int gFirst, int nG) {
    int gid = blockIdx.x * blockDim.x + threadIdx.x;
    if (gid >= nG * 128 * 256) return;
    int gl = gid >> 15;
    int rem = gid & 32767;
    int n = rem >> 8;
    int k = rem & 255;
    const float* W;
    if (gl == 0) W = (k < 128) ? wl0 : wr0;
    else         W = (k < 128) ? wl1 : wr1;
    float v = W[(size_t)(k & 127) * CC + n];
    __nv_bfloat16 h = __float2bfloat16(v);
    __nv_bfloat16 l = __float2bfloat16(v - __bfloat162float(h));
    int g = gFirst + gl;
    int dst = (g << 15) + (n << 8) + k;
    wh[dst] = h;
    wl[dst] = l;
}

// ---------------------------------------------------------------------------
#define ROW_B 80

// Transform GEMM: half 0 writes fp16 yl16; half 1 writes fp32 yr (+bias).
__global__ __launch_bounds__(256, 2) void gemm_t_kernel(
    const float* __restrict__ X,
    const __nv_bfloat16* __restrict__ wh, const __nv_bfloat16* __restrict__ wl,
    const float* __restrict__ bias,
    __half* __restrict__ yl16, float* __restrict__ yr, int M) {

    __shared__ __align__(16) char sA_hi[128 * ROW_B];
    __shared__ __align__(16) char sA_lo[128 * ROW_B];
    __shared__ __align__(16) char sB_hi[128 * ROW_B];
    __shared__ __align__(16) char sB_lo[128 * ROW_B];

    const int tid = threadIdx.x;
    const int lane = tid & 31;
    const int wid = tid >> 5;
    const int wm = (wid & 3) * 32;
    const int wn = (wid >> 2) * 64;
    const int row0 = blockIdx.x * 128;
    const int half = blockIdx.y;

    float acc[2][8][4] = {};

    const uint32_t aHi = smem_u32(sA_hi), aLo = smem_u32(sA_lo);
    const uint32_t bHi = smem_u32(sB_hi), bLo = smem_u32(sB_lo);

    const int a_mrow = ((lane >> 3) & 1) * 8 + (lane & 7);
    const int a_j = lane >> 4;
    const int b_nrow = (lane >> 4) * 8 + (lane & 7);
    const int b_j = (lane >> 3) & 1;

    float4 vA[4];

    auto loadA = [&](int c) {
        const int koff = c * 32;
#pragma unroll
        for (int i = 0; i < 4; i++) {
            int idx = tid + (i << 8);
            int m = idx >> 3, k4 = idx & 7;
            int row = row0 + m;
            vA[i] = (row < M) ? *(const float4*)(X + (size_t)row * CC + koff + (k4 << 2))
                              : make_float4(0.f, 0.f, 0.f, 0.f);
        }
    };

    loadA(0);

    for (int c = 0; c < 4; c++) {
        const int cb = half * 4 + c;
#pragma unroll
        for (int i = 0; i < 2; i++) {
            int idx = tid + (i << 8);
            int n = idx >> 2, j = idx & 3;
            size_t srcOff = (size_t)n * 512 + (size_t)cb * 64 + (size_t)j * 16;
            cp_async16(bHi + n * ROW_B + (j << 4), (const char*)wh + srcOff);
            cp_async16(bLo + n * ROW_B + (j << 4), (const char*)wl + srcOff);
        }
        asm volatile("cp.async.commit_group;" ::: "memory");

#pragma unroll
        for (int i = 0; i < 4; i++) {
            int idx = tid + (i << 8);
            int m = idx >> 3, k4 = idx & 7;
            float x0 = vA[i].x, x1 = vA[i].y, x2 = vA[i].z, x3 = vA[i].w;
            __nv_bfloat162 h01 = make_bfloat162(__float2bfloat16(x0), __float2bfloat16(x1));
            __nv_bfloat162 h23 = make_bfloat162(__float2bfloat16(x2), __float2bfloat16(x3));
            __nv_bfloat162 l01 = make_bfloat162(
                __float2bfloat16(x0 - __bfloat162float(h01.x)),
                __float2bfloat16(x1 - __bfloat162float(h01.y)));
            __nv_bfloat162 l23 = make_bfloat162(
                __float2bfloat16(x2 - __bfloat162float(h23.x)),
                __float2bfloat16(x3 - __bfloat162float(h23.y)));
            char* pd = sA_hi + m * ROW_B + (k4 << 3);
            *(__nv_bfloat162*)(pd + 0) = h01;
            *(__nv_bfloat162*)(pd + 4) = h23;
            char* pl = sA_lo + m * ROW_B + (k4 << 3);
            *(__nv_bfloat162*)(pl + 0) = l01;
            *(__nv_bfloat162*)(pl + 4) = l23;
        }

        if (c < 3) loadA(c + 1);

        asm volatile("cp.async.wait_group 0;" ::: "memory");
        __syncthreads();

#pragma unroll
        for (int ks = 0; ks < 2; ks++) {
            uint32_t ah[8], al[8];
#pragma unroll
            for (int mi = 0; mi < 2; mi++) {
                uint32_t off = (uint32_t)((wm + mi * 16 + a_mrow) * ROW_B + ks * 32 + a_j * 16);
                ldsm_x4(ah[mi * 4 + 0], ah[mi * 4 + 1], ah[mi * 4 + 2], ah[mi * 4 + 3], aHi + off);
                ldsm_x4(al[mi * 4 + 0], al[mi * 4 + 1], al[mi * 4 + 2], al[mi * 4 + 3], aLo + off);
            }
#pragma unroll
            for (int bg = 0; bg < 4; bg++) {
                uint32_t off = (uint32_t)((wn + bg * 16 + b_nrow) * ROW_B + ks * 32 + b_j * 16);
                uint32_t bh0, bh1, bh2, bh3, bl0, bl1, bl2, bl3;
                ldsm_x4(bh0, bh1, bh2, bh3, bHi + off);
                ldsm_x4(bl0, bl1, bl2, bl3, bLo + off);
#pragma unroll
                for (int mi = 0; mi < 2; mi++) {
                    mma_bf16(acc[mi][bg * 2 + 0], ah + mi * 4, bh0, bh1);
                    mma_bf16(acc[mi][bg * 2 + 0], ah + mi * 4, bl0, bl1);
                    mma_bf16(acc[mi][bg * 2 + 0], al + mi * 4, bh0, bh1);
                    mma_bf16(acc[mi][bg * 2 + 1], ah + mi * 4, bh2, bh3);
                    mma_bf16(acc[mi][bg * 2 + 1], ah + mi * 4, bl2, bl3);
                    mma_bf16(acc[mi][bg * 2 + 1], al + mi * 4, bh2, bh3);
                }
            }
        }
        __syncthreads();
    }

    const int rbase = row0 + wm + (lane >> 2);
    const int cbase = wn + (lane & 3) * 2;
    if (half == 0) {
        // fp16 store (2 halves = 4B, col even so 4B-aligned)
#pragma unroll
        for (int mi = 0; mi < 2; mi++) {
#pragma unroll
            for (int ni = 0; ni < 8; ni++) {
                int col = cbase + ni * 8;
                int r1 = rbase + mi * 16, r2 = r1 + 8;
                if (r1 < M) *(__half2*)(yl16 + (size_t)r1 * CC + col) =
                    __floats2half2_rn(acc[mi][ni][0], acc[mi][ni][1]);
                if (r2 < M) *(__half2*)(yl16 + (size_t)r2 * CC + col) =
                    __floats2half2_rn(acc[mi][ni][2], acc[mi][ni][3]);
            }
        }
    } else {
        const bool addB = (bias != nullptr);
#pragma unroll
        for (int mi = 0; mi < 2; mi++) {
#pragma unroll
            for (int ni = 0; ni < 8; ni++) {
                int col = cbase + ni * 8;
                float b0 = addB ? __ldg(bias + col) : 0.f;
                float b1 = addB ? __ldg(bias + col + 1) : 0.f;
                int r1 = rbase + mi * 16, r2 = r1 + 8;
                if (r1 < M) *(float2*)(yr + (size_t)r1 * CC + col) =
                    make_float2(acc[mi][ni][0] + b0, acc[mi][ni][1] + b1);
                if (r2 < M) *(float2*)(yr + (size_t)r2 * CC + col) =
                    make_float2(acc[mi][ni][2] + b0, acc[mi][ni][3] + b1);
            }
        }
    }
}

// ---------------------------------------------------------------------------
// Final GEMM: out = [A0|A1] (Mx256) @ Wt^T + bias
__global__ __launch_bounds__(256, 2) void gemm_mma_kernel(
    const float* __restrict__ A0, const float* __restrict__ A1,
    const __nv_bfloat16* __restrict__ wh, const __nv_bfloat16* __restrict__ wl,
    const float* __restrict__ bias,
    float* __restrict__ out, int M) {

    __shared__ __align__(16) char sA_hi[128 * ROW_B];
    __shared__ __align__(16) char sA_lo[128 * ROW_B];
    __shared__ __align__(16) char sB_hi[128 * ROW_B];
    __shared__ __align__(16) char sB_lo[128 * ROW_B];

    const int tid = threadIdx.x;
    const int lane = tid & 31;
    const int wid = tid >> 5;
    const int wm = (wid & 3) * 32;
    const int wn = (wid >> 2) * 64;
    const int row0 = blockIdx.x * 128;

    float acc[2][8][4] = {};

    const uint32_t aHi = smem_u32(sA_hi), aLo = smem_u32(sA_lo);
    const uint32_t bHi = smem_u32(sB_hi), bLo = smem_u32(sB_lo);

    const int a_mrow = ((lane >> 3) & 1) * 8 + (lane & 7);
    const int a_j = lane >> 4;
    const int b_nrow = (lane >> 4) * 8 + (lane & 7);
    const int b_j = (lane >> 3) & 1;

    float4 vA[4];

    auto loadA = [&](int c) {
        const float* SA = (c < 4) ? A0 : A1;
        const int koff = (c & 3) * 32;
#pragma unroll
        for (int i = 0; i < 4; i++) {
            int idx = tid + (i << 8);
            int m = idx >> 3, k4 = idx & 7;
            int row = row0 + m;
            vA[i] = (row < M) ? *(const float4*)(SA + (size_t)row * CC + koff + (k4 << 2))
                              : make_float4(0.f, 0.f, 0.f, 0.f);
        }
    };

    loadA(0);

    for (int c = 0; c < 8; c++) {
#pragma unroll
        for (int i = 0; i < 2; i++) {
            int idx = tid + (i << 8);
            int n = idx >> 2, j = idx & 3;
            size_t srcOff = (size_t)n * 512 + (size_t)c * 64 + (size_t)j * 16;
            cp_async16(bHi + n * ROW_B + (j << 4), (const char*)wh + srcOff);
            cp_async16(bLo + n * ROW_B + (j << 4), (const char*)wl + srcOff);
        }
        asm volatile("cp.async.commit_group;" ::: "memory");

#pragma unroll
        for (int i = 0; i < 4; i++) {
            int idx = tid + (i << 8);
            int m = idx >> 3, k4 = idx & 7;
            float x0 = vA[i].x, x1 = vA[i].y, x2 = vA[i].z, x3 = vA[i].w;
            __nv_bfloat162 h01 = make_bfloat162(__float2bfloat16(x0), __float2bfloat16(x1));
            __nv_bfloat162 h23 = make_bfloat162(__float2bfloat16(x2), __float2bfloat16(x3));
            __nv_bfloat162 l01 = make_bfloat162(
                __float2bfloat16(x0 - __bfloat162float(h01.x)),
                __float2bfloat16(x1 - __bfloat162float(h01.y)));
            __nv_bfloat162 l23 = make_bfloat162(
                __float2bfloat16(x2 - __bfloat162float(h23.x)),
                __float2bfloat16(x3 - __bfloat162float(h23.y)));
            char* pd = sA_hi + m * ROW_B + (k4 << 3);
            *(__nv_bfloat162*)(pd + 0) = h01;
            *(__nv_bfloat162*)(pd + 4) = h23;
            char* pl = sA_lo + m * ROW_B + (k4 << 3);
            *(__nv_bfloat162*)(pl + 0) = l01;
            *(__nv_bfloat162*)(pl + 4) = l23;
        }

        if (c < 7) loadA(c + 1);

        asm volatile("cp.async.wait_group 0;" ::: "memory");
        __syncthreads();

#pragma unroll
        for (int ks = 0; ks < 2; ks++) {
            uint32_t ah[8], al[8];
#pragma unroll
            for (int mi = 0; mi < 2; mi++) {
                uint32_t off = (uint32_t)((wm + mi * 16 + a_mrow) * ROW_B + ks * 32 + a_j * 16);
                ldsm_x4(ah[mi * 4 + 0], ah[mi * 4 + 1], ah[mi * 4 + 2], ah[mi * 4 + 3], aHi + off);
                ldsm_x4(al[mi * 4 + 0], al[mi * 4 + 1], al[mi * 4 + 2], al[mi * 4 + 3], aLo + off);
            }
#pragma unroll
            for (int bg = 0; bg < 4; bg++) {
                uint32_t off = (uint32_t)((wn + bg * 16 + b_nrow) * ROW_B + ks * 32 + b_j * 16);
                uint32_t bh0, bh1, bh2, bh3, bl0, bl1, bl2, bl3;
                ldsm_x4(bh0, bh1, bh2, bh3, bHi + off);
                ldsm_x4(bl0, bl1, bl2, bl3, bLo + off);
#pragma unroll
                for (int mi = 0; mi < 2; mi++) {
                    mma_bf16(acc[mi][bg * 2 + 0], ah + mi * 4, bh0, bh1);
                    mma_bf16(acc[mi][bg * 2 + 0], ah + mi * 4, bl0, bl1);
                    mma_bf16(acc[mi][bg * 2 + 0], al + mi * 4, bh0, bh1);
                    mma_bf16(acc[mi][bg * 2 + 1], ah + mi * 4, bh2, bh3);
                    mma_bf16(acc[mi][bg * 2 + 1], ah + mi * 4, bl2, bl3);
                    mma_bf16(acc[mi][bg * 2 + 1], al + mi * 4, bh2, bh3);
                }
            }
        }
        __syncthreads();
    }

    const int rbase = row0 + wm + (lane >> 2);
    const int cbase = wn + (lane & 3) * 2;
#pragma unroll
    for (int mi = 0; mi < 2; mi++) {
#pragma unroll
        for (int ni = 0; ni < 8; ni++) {
            int col = cbase + ni * 8;
            float b0 = __ldg(bias + col), b1 = __ldg(bias + col + 1);
            int r1 = rbase + mi * 16, r2 = r1 + 8;
            if (r1 < M) *(float2*)(out + (size_t)r1 * CC + col) =
                make_float2(acc[mi][ni][0] + b0, acc[mi][ni][1] + b1);
            if (r2 < M) *(float2*)(out + (size_t)r2 * CC + col) =
                make_float2(acc[mi][ni][2] + b0, acc[mi][ni][3] + b1);
        }
    }
}

// ---------------------------------------------------------------------------
extern "C" void kernel_launch(void* const* d_in, const int* in_sizes, int n_in,
                              void* d_out, int out_size) {
    const float* x     = (const float*)d_in[0];
    const int*   ei    = (const int*)d_in[1];     // int32
    const float* W1_l  = (const float*)d_in[2];
    const float* b1_l  = (const float*)d_in[3];
    const float* W1_r  = (const float*)d_in[4];
    const float* W2_l  = (const float*)d_in[5];
    const float* b2_l  = (const float*)d_in[6];
    const float* W2_r  = (const float*)d_in[7];
    const float* W_lin = (const float*)d_in[8];
    const float* b_lin = (const float*)d_in[9];
    float* out = (float*)d_out;

    const int M = in_sizes[0] / CC;      // 50000
    const int E = in_sizes[1] / 2;       // 600000

    float *x1, *x2, *yr;
    __half* yl16;
    int *cnt, *rs, *cur, *csr, *part;
    __nv_bfloat16 *wbh, *wbl;
    cudaGetSymbolAddress((void**)&x1, g_x1);
    cudaGetSymbolAddress((void**)&x2, g_x2);
    cudaGetSymbolAddress((void**)&yl16, g_yl16);
    cudaGetSymbolAddress((void**)&yr, g_yr);
    cudaGetSymbolAddress((void**)&cnt, g_cnt);
    cudaGetSymbolAddress((void**)&rs, g_rs);
    cudaGetSymbolAddress((void**)&cur, g_cur);
    cudaGetSymbolAddress((void**)&csr, g_csr);
    cudaGetSymbolAddress((void**)&part, g_part);
    cudaGetSymbolAddress((void**)&wbh, g_wbh);
    cudaGetSymbolAddress((void**)&wbl, g_wbl);

    // side stream + events (created once, on the un-captured correctness call)
    static cudaStream_t s2 = nullptr;
    static cudaEvent_t evF = nullptr, evCSR = nullptr;
    if (!s2) {
        cudaStreamCreateWithFlags(&s2, cudaStreamNonBlocking);
        cudaEventCreateWithFlags(&evF, cudaEventDisableTiming);
        cudaEventCreateWithFlags(&evCSR, cudaEventDisableTiming);
    }

    const int TB = 256;
    const int gemmBlocks = (M + 127) / 128;          // 391
    const int combBlocks = (M * 32 + TB - 1) / TB;
    const int edgeBlocks = (E + TB - 1) / TB;
    const int nScanBlk = (M + 511) / 512;            // 98

    // ---- fork: prep(gemm1,2) + CSR build on s2; prep(gemm0) + gemmT1 on main ----
    cudaEventRecord(evF, 0);
    cudaStreamWaitEvent(s2, evF, 0);

    prep_w_kernel<<<256, TB, 0, s2>>>(W2_l, W2_r, W_lin, W_lin + 128 * CC,
                                      wbh, wbl, 1, 2);
    cudaMemsetAsync(cnt, 0, (size_t)M * sizeof(int), s2);
    count_kernel<<<edgeBlocks, TB, 0, s2>>>(ei, cnt, E);
    scan_local_kernel<<<nScanBlk, 512, 0, s2>>>(cnt, rs, part, M);
    scan_add_kernel<<<nScanBlk, 512, 0, s2>>>(rs, part, cur, M, nScanBlk);
    fill_kernel<<<edgeBlocks, TB, 0, s2>>>(ei, cur, csr, E);
    cudaEventRecord(evCSR, s2);

    prep_w_kernel<<<128, TB>>>(W1_l, W1_r, nullptr, nullptr, wbh, wbl, 0, 1);
    gemm_t_kernel<<<dim3(gemmBlocks, 2), TB>>>(x, wbh, wbl, b1_l, yl16, yr, M);

    cudaStreamWaitEvent(0, evCSR, 0);

    // ---- layer 1 combine: x1 = relu(mean_agg(Y1_l fp16) + (Y1_r + b1)) ----
    combine_kernel<<<combBlocks, TB>>>(yl16, yr, csr, rs, cnt, x1, M);

    // ---- layer 2 ----
    gemm_t_kernel<<<dim3(gemmBlocks, 2), TB>>>(x1, wbh + 32768, wbl + 32768, b2_l, yl16, yr, M);
    combine_kernel<<<combBlocks, TB>>>(yl16, yr, csr, rs, cnt, x2, M);

    // ---- final linear: [x1 | x2] @ W_lin + b_lin ----
    gemm_mma_kernel<<<gemmBlocks, TB>>>(x1, x2, wbh + 65536, wbl + 65536, b_lin, out, M);
}